// round 5
// baseline (speedup 1.0000x reference)
#include <cuda_runtime.h>
#include <cstdint>

#define BB 8
#define CC 256
#define HH 160
#define WW 160
#define HW (HH*WW)          // 25600
#define NG 8                // channel groups
#define CPG 32              // channels per group
#define NCI 4               // channels per smem iteration
#define ETW 32              // edge tile width
#define ETH 32              // edge tile height
#define HALO_W 34
#define HALO_E (HALO_W*HALO_W)   // 1156 per channel

// ---- scratch (no allocations allowed) ----
__device__ float    g_c_sum[BB*CC];       // per-(b,c) sum of g
__device__ float    g_w_gate[BB*CC];      // channel gate
__device__ float    g_sum_x[BB*HW];       // per-pixel sum over channels of x
__device__ float    g_sum_g[BB*HW];       // per-pixel sum over channels of g
__device__ unsigned g_max_x[BB*HW];       // ordered-uint max of x
__device__ unsigned g_max_g[BB*HW];       // ordered-uint max of g
__device__ float    g_s_map[BB*HW];       // spatial gate
__device__ float    g_ab[2];              // softplus(alpha), softplus(beta)

// monotone float<->uint order map
__device__ __forceinline__ unsigned omap(float f) {
    unsigned u = __float_as_uint(f);
    return (u & 0x80000000u) ? ~u : (u | 0x80000000u);
}
__device__ __forceinline__ float ounmap(unsigned u) {
    return __uint_as_float((u & 0x80000000u) ? (u ^ 0x80000000u) : ~u);
}

__global__ void zero_kernel() {
    int i = blockIdx.x * 256 + threadIdx.x;
    if (i < BB*HW) {
        g_sum_x[i] = 0.f; g_sum_g[i] = 0.f;
        g_max_x[i] = 0u;  g_max_g[i] = 0u;   // 0 is below every mapped float
    }
    if (i < BB*CC) g_c_sum[i] = 0.f;
}

// ---------------------------------------------------------------------------
// Kernel 1: Sobel magnitude + reductions.
// grid (5, 5, B*NG), block 256; 32x32 tile, 4 vertical px/thread,
// 4 channels per smem iteration, 8 iterations (CPG=32).
// ---------------------------------------------------------------------------
__global__ __launch_bounds__(256) void k_edge(const float* __restrict__ x) {
    __shared__ float xs[NCI*HALO_E];      // 4 x 1156 = 18.5 KB
    __shared__ float cpartg[CPG];

    const int tid  = threadIdx.x;
    const int lane = tid & 31;
    const int tx0  = blockIdx.x * ETW;
    const int ty0  = blockIdx.y * ETH;
    const int bz   = blockIdx.z;
    const int b    = bz >> 3;             // NG = 8
    const int cbase = (bz & 7) * CPG;

    if (tid < CPG) cpartg[tid] = 0.f;

    // per-channel halo = 1156 elems = 4*256 + 132; 5 channel-invariant offsets
    int off[5];
    #pragma unroll
    for (int k = 0; k < 5; k++) {
        int i   = tid + k * 256;
        int r   = i / HALO_W, cc2 = i - r * HALO_W;
        int gy  = ty0 - 1 + r, gx = tx0 - 1 + cc2;
        bool ok = (i < HALO_E) && ((unsigned)gy < HH) && ((unsigned)gx < WW);
        off[k] = ok ? (gy * WW + gx) : -1;
    }

    const int pc    = lane;
    const int pr0   = (tid >> 5) * 4;     // 4 vertical px/thread
    const int sbase = pr0 * HALO_W + pc;

    float sumx[4], sumg[4], maxx[4], maxg[4];
    #pragma unroll
    for (int p = 0; p < 4; p++) {
        sumx[p] = 0.f; sumg[p] = 0.f; maxx[p] = -3.4e38f; maxg[p] = 0.f;
    }

    const float* xg = x + ((size_t)b * CC + cbase) * HW;
    for (int c0 = 0; c0 < CPG; c0 += NCI) {
        #pragma unroll
        for (int ch = 0; ch < NCI; ch++) {
            const float* xc = xg + (size_t)(c0 + ch) * HW;
            float* xsp = xs + ch * HALO_E;
            #pragma unroll
            for (int k = 0; k < 4; k++)
                xsp[tid + k*256] = (off[k] >= 0) ? xc[off[k]] : 0.f;
            if (tid < HALO_E - 4*256)
                xsp[tid + 4*256] = (off[4] >= 0) ? xc[off[4]] : 0.f;
        }
        __syncthreads();

        float part[NCI];
        #pragma unroll
        for (int ci = 0; ci < NCI; ci++) {
            const float* xsp = xs + ci * HALO_E;
            // vs[p][j], vd[p][j]: vertical smooth/diff for 4 px, 3 cols
            float vs[4][3], vd[4][3], xc_[4];
            #pragma unroll
            for (int j = 0; j < 3; j++) {
                float a0 = xsp[sbase + j];
                float a1 = xsp[sbase + HALO_W + j];
                float a2 = xsp[sbase + 2*HALO_W + j];
                float a3 = xsp[sbase + 3*HALO_W + j];
                float a4 = xsp[sbase + 4*HALO_W + j];
                float a5 = xsp[sbase + 5*HALO_W + j];
                vs[0][j] = fmaf(2.f, a1, a0) + a2;  vd[0][j] = a0 - a2;
                vs[1][j] = fmaf(2.f, a2, a1) + a3;  vd[1][j] = a1 - a3;
                vs[2][j] = fmaf(2.f, a3, a2) + a4;  vd[2][j] = a2 - a4;
                vs[3][j] = fmaf(2.f, a4, a3) + a5;  vd[3][j] = a3 - a5;
                if (j == 1) { xc_[0] = a1; xc_[1] = a2; xc_[2] = a3; xc_[3] = a4; }
            }
            float gsum = 0.f;
            #pragma unroll
            for (int p = 0; p < 4; p++) {
                float gx = 0.25f * (vs[p][0] - vs[p][2]);
                float gy = 0.25f * (fmaf(2.f, vd[p][1], vd[p][0]) + vd[p][2]);
                float g  = sqrtf(fmaf(gy, gy, fmaf(gx, gx, 1e-12f)));
                sumx[p] += xc_[p];  maxx[p] = fmaxf(maxx[p], xc_[p]);
                sumg[p] += g;       maxg[p] = fmaxf(maxg[p], g);
                gsum += g;
            }
            part[ci] = gsum;
        }

        // multi-value butterfly: 4 channel sums in 6 shfls.
        bool hi16 = (lane & 16), hi8 = (lane & 8);
        float sA = hi16 ? part[0] : part[2];
        float rA = __shfl_xor_sync(0xffffffffu, sA, 16);
        float sB = hi16 ? part[1] : part[3];
        float rB = __shfl_xor_sync(0xffffffffu, sB, 16);
        float v0 = (hi16 ? part[2] : part[0]) + rA;
        float v1 = (hi16 ? part[3] : part[1]) + rB;
        float sC = hi8 ? v0 : v1;
        float rC = __shfl_xor_sync(0xffffffffu, sC, 8);
        float v  = (hi8 ? v1 : v0) + rC;
        v += __shfl_xor_sync(0xffffffffu, v, 4);
        v += __shfl_xor_sync(0xffffffffu, v, 2);
        v += __shfl_xor_sync(0xffffffffu, v, 1);
        if ((lane & 7) == 0)
            atomicAdd(&cpartg[c0 + (lane >> 3)], v);
        __syncthreads();
    }

    // per-pixel partial combine across channel groups
    #pragma unroll
    for (int p = 0; p < 4; p++) {
        int pp = b * HW + (ty0 + pr0 + p) * WW + tx0 + pc;
        atomicAdd(&g_sum_x[pp], sumx[p]);
        atomicAdd(&g_sum_g[pp], sumg[p]);
        atomicMax(&g_max_x[pp], omap(maxx[p]));
        atomicMax(&g_max_g[pp], omap(maxg[p]));
    }
    if (tid < CPG) atomicAdd(&g_c_sum[b*CC + cbase + tid], cpartg[tid]);
}

// ---------------------------------------------------------------------------
// Kernel 2: fused gates. Blocks 0..799: spatial 7x7 conv (16x16 tiles).
// Blocks 800..807: channel MLP for batch (blk-800). block = 256.
// ---------------------------------------------------------------------------
#define STILE 16
#define SHALO 22
#define SHE (SHALO*SHALO)    // 484
__global__ __launch_bounds__(256) void k_gates(const float* __restrict__ w1,
                                               const float* __restrict__ w2,
                                               const float* __restrict__ sw,
                                               const float* __restrict__ sb,
                                               const float* __restrict__ alpha,
                                               const float* __restrict__ beta) {
    __shared__ float sm[4*SHE + 200];     // spatial: tiles+weights; mlp: cv+h
    const int tid = threadIdx.x;
    const int blk = blockIdx.x;

    if (blk < 800) {
        // ---- spatial gate ----
        const int bx = blk % 10, by = (blk / 10) % 10, b = blk / 100;
        const int tx0 = bx * STILE, ty0 = by * STILE;
        float* t   = sm;
        float* wsm = sm + 4*SHE;
        if (tid < 196) wsm[tid] = sw[tid];

        const int pbase = b * HW;
        const float invC = 1.f / CC;
        for (int i = tid; i < 4*SHE; i += 256) {
            int ch  = i / SHE;
            int rem = i - ch * SHE;
            int r   = rem / SHALO, cc2 = rem - r * SHALO;
            int gy  = ty0 - 3 + r, gx = tx0 - 3 + cc2;
            float v = 0.f;
            if ((unsigned)gy < HH && (unsigned)gx < WW) {
                int p = pbase + gy * WW + gx;
                if      (ch == 0) v = g_sum_x[p] * invC;
                else if (ch == 1) v = ounmap(g_max_x[p]);
                else if (ch == 2) v = g_sum_g[p] * invC;
                else              v = ounmap(g_max_g[p]);
            }
            t[i] = v;
        }
        __syncthreads();

        const int pr = tid >> 4, pc = tid & 15;
        float acc = sb[0];
        #pragma unroll
        for (int ch = 0; ch < 4; ch++) {
            #pragma unroll
            for (int u = 0; u < 7; u++) {
                const float* rp = &t[ch*SHE + (pr + u)*SHALO + pc];
                const float* wr = &wsm[ch*49 + u*7];
                #pragma unroll
                for (int v = 0; v < 7; v++) acc = fmaf(rp[v], wr[v], acc);
            }
        }
        g_s_map[pbase + (ty0 + pr)*WW + tx0 + pc] = 1.f / (1.f + __expf(-acc));
    } else {
        // ---- channel MLP gate ----
        const int b = blk - 800;
        float* cv = sm;
        float* h  = sm + CC;
        cv[tid] = g_c_sum[b*CC + tid] * (1.f / HW);
        __syncthreads();
        if (tid < 16) {
            float acc = 0.f;
            for (int c2 = 0; c2 < CC; c2++) acc = fmaf(cv[c2], w1[tid*CC + c2], acc);
            h[tid] = fmaxf(acc, 0.f);
        }
        __syncthreads();
        float acc = 0.f;
        #pragma unroll
        for (int j = 0; j < 16; j++) acc = fmaf(h[j], w2[tid*16 + j], acc);
        g_w_gate[b*CC + tid] = 1.f / (1.f + __expf(-acc));
        if (b == 0 && tid == 0) {
            float av = alpha[0], bv = beta[0];
            g_ab[0] = (av > 20.f) ? av : log1pf(expf(av));
            g_ab[1] = (bv > 20.f) ? bv : log1pf(expf(bv));
        }
    }
}

// ---------------------------------------------------------------------------
// Kernel 3: streaming apply. out = x * (1 + a*s) * (1 + b*w). float4.
// ---------------------------------------------------------------------------
__global__ __launch_bounds__(256) void k_apply(const float* __restrict__ x,
                                               float* __restrict__ out) {
    const float a  = g_ab[0];
    const float bb = g_ab[1];
    const int hw4  = HW / 4;             // 6400
    const int chw4 = CC * hw4;           // 1638400
    int i4 = blockIdx.x * 256 + threadIdx.x;
    int b  = i4 / chw4;
    int r  = i4 - b * chw4;
    int c  = r / hw4;
    int p4 = r - c * hw4;
    float wg = fmaf(bb, g_w_gate[b*CC + c], 1.f);
    float4 s4 = ((const float4*)g_s_map)[b*hw4 + p4];
    float4 x4 = ((const float4*)x)[i4];
    float4 o;
    o.x = x4.x * fmaf(a, s4.x, 1.f) * wg;
    o.y = x4.y * fmaf(a, s4.y, 1.f) * wg;
    o.z = x4.z * fmaf(a, s4.z, 1.f) * wg;
    o.w = x4.w * fmaf(a, s4.w, 1.f) * wg;
    ((float4*)out)[i4] = o;
}

// ---------------------------------------------------------------------------
extern "C" void kernel_launch(void* const* d_in, const int* in_sizes, int n_in,
                              void* d_out, int out_size) {
    const float* x  = (const float*)d_in[0];
    const float* w1 = (const float*)d_in[1];
    const float* w2 = (const float*)d_in[2];
    const float* sw = (const float*)d_in[3];
    const float* sb = (const float*)d_in[4];
    const float* al = (const float*)d_in[5];
    const float* be = (const float*)d_in[6];
    float* out = (float*)d_out;

    zero_kernel<<<(BB*HW + 255)/256, 256>>>();
    dim3 g1(WW/ETW, HH/ETH, BB*NG);
    k_edge<<<g1, 256>>>(x);
    k_gates<<<808, 256>>>(w1, w2, sw, sb, al, be);
    int total4 = BB * CC * HW / 4;
    k_apply<<<(total4 + 255)/256, 256>>>(x, out);
}

// round 7
// speedup vs baseline: 1.0600x; 1.0600x over previous
#include <cuda_runtime.h>
#include <cstdint>

#define BB 8
#define CC 256
#define HH 160
#define WW 160
#define HW (HH*WW)          // 25600

// edge kernel geometry: strip = 30 cols x 8 rows, 8 warps split 256 channels
#define OTW 30              // output cols per strip
#define OTH 8               // output rows per strip
#define NXT 6               // x tiles (6*30=180 covers 160)
#define NYT 20              // y tiles (20*8=160)
#define CPW 32              // channels per warp

// ---- scratch (no allocations allowed) ----
__device__ float g_c_sum[BB*CC];      // per-(b,c) sum of g (atomic across 120 tiles)
__device__ float g_w_gate[BB*CC];     // channel gate
__device__ float g_sum_x[BB*HW];      // per-pixel sum over channels of x
__device__ float g_sum_g[BB*HW];      // per-pixel sum over channels of g
__device__ float g_max_x[BB*HW];      // per-pixel max of x
__device__ float g_max_g[BB*HW];      // per-pixel max of g
__device__ float g_s_map[BB*HW];      // spatial gate
__device__ float g_ab[2];             // softplus(alpha), softplus(beta)

__device__ __forceinline__ float sqrt_approx(float v) {
    float r;
    asm("sqrt.approx.f32 %0, %1;" : "=f"(r) : "f"(v));
    return r;
}

__global__ void zero_kernel() {
    int i = blockIdx.x * 256 + threadIdx.x;
    if (i < BB*CC) g_c_sum[i] = 0.f;
}

// ---------------------------------------------------------------------------
// Kernel 1: Sobel magnitude + all reductions. No smem / no barriers in the
// channel loop: horizontal stage via warp shuffles, vertical stage via a
// 3-row register window. 8 warps x 32 channels over one 30x8 pixel strip;
// cross-warp (cross-channel) combine via one smem pass; plain stores.
// grid (NXT, NYT, BB), block 256.
// ---------------------------------------------------------------------------
__global__ __launch_bounds__(256) void k_edge(const float* __restrict__ x) {
    __shared__ float cmb[4*8*OTW*OTH];      // [val][warp][px], 30.7 KB

    const int tid  = threadIdx.x;
    const int lane = tid & 31;
    const int wid  = tid >> 5;
    const int tx0  = blockIdx.x * OTW;
    const int ry0  = blockIdx.y * OTH;
    const int b    = blockIdx.z;

    const int col   = tx0 + lane - 1;       // lane L <-> col tx0+L-1
    const bool colok = ((unsigned)col < WW);
    const bool outlane = (lane >= 1 && lane <= 30);

    float sx[OTH], sg[OTH], mx[OTH], mg[OTH];
    #pragma unroll
    for (int k = 0; k < OTH; k++) {
        sx[k] = 0.f; sg[k] = 0.f; mx[k] = -3.4e38f; mg[k] = 0.f;
    }

    // row validity (channel-invariant): rows ry0-1 .. ry0+8
    const int   r_m1 = ry0 - 1;
    const bool  rm1ok = (r_m1 >= 0);
    const bool  rp8ok = (ry0 + OTH < HH);   // row ry0+8

    const float* xb = x + ((size_t)b * CC + (size_t)wid * CPW) * HW;

    for (int ch = 0; ch < CPW; ch++) {
        const float* xc = xb + (size_t)ch * HW + col;
        float cs = 0.f;

        // prologue rows i=0 (ry0-1), i=1 (ry0)
        float v, xl, xr;
        v  = (colok && rm1ok) ? xc[(size_t)r_m1 * WW] : 0.f;
        xl = __shfl_up_sync(0xffffffffu, v, 1);
        xr = __shfl_down_sync(0xffffffffu, v, 1);
        float hdA = xl - xr;
        float hsA = fmaf(2.f, v, xl) + xr;

        v  = colok ? xc[(size_t)ry0 * WW] : 0.f;
        xl = __shfl_up_sync(0xffffffffu, v, 1);
        xr = __shfl_down_sync(0xffffffffu, v, 1);
        float hdB = xl - xr;
        float hsB = fmaf(2.f, v, xl) + xr;
        float xprev = v;

        #pragma unroll
        for (int k = 0; k < OTH; k++) {
            bool rok = (k < OTH-1) || rp8ok;      // row ry0+k+1
            v  = (colok && rok) ? xc[(size_t)(ry0 + k + 1) * WW] : 0.f;
            xl = __shfl_up_sync(0xffffffffu, v, 1);
            xr = __shfl_down_sync(0xffffffffu, v, 1);
            float hdC = xl - xr;
            float hsC = fmaf(2.f, v, xl) + xr;

            float gx = fmaf(2.f, hdB, hdA) + hdC;  // 4*true gx
            float gy = hsA - hsC;                  // 4*true gy
            float g  = 0.25f * sqrt_approx(fmaf(gy, gy, fmaf(gx, gx, 1.6e-11f)));

            sx[k] += xprev;  mx[k] = fmaxf(mx[k], xprev);
            sg[k] += g;      mg[k] = fmaxf(mg[k], g);
            cs += g;

            hdA = hdB; hdB = hdC; hsA = hsB; hsB = hsC; xprev = v;
        }

        // per-channel spatial sum: lanes 1..30 only, butterfly + atomic
        if (!outlane || !colok) cs = 0.f;
        #pragma unroll
        for (int off = 16; off; off >>= 1)
            cs += __shfl_xor_sync(0xffffffffu, cs, off);
        if (lane == 0)
            atomicAdd(&g_c_sum[b*CC + wid*CPW + ch], cs);
    }

    // cross-warp combine of per-pixel stats (one pass)
    if (outlane) {
        const int pxb = lane - 1;
        #pragma unroll
        for (int k = 0; k < OTH; k++) {
            int px = k * OTW + pxb;
            cmb[(0*8 + wid)*(OTW*OTH) + px] = sx[k];
            cmb[(1*8 + wid)*(OTW*OTH) + px] = mx[k];
            cmb[(2*8 + wid)*(OTW*OTH) + px] = sg[k];
            cmb[(3*8 + wid)*(OTW*OTH) + px] = mg[k];
        }
    }
    __syncthreads();

    const int NPX = OTW * OTH;              // 240
    for (int i = tid; i < 4*NPX; i += 256) {
        int val = i / NPX;
        int px  = i - val * NPX;
        bool ismax = (val & 1);
        float r = cmb[(val*8 + 0)*NPX + px];
        #pragma unroll
        for (int w = 1; w < 8; w++) {
            float t = cmb[(val*8 + w)*NPX + px];
            r = ismax ? fmaxf(r, t) : (r + t);
        }
        int prow = px / OTW, pcol = px - prow * OTW;
        int gcol = tx0 + pcol;
        if (gcol < WW) {
            int p = b * HW + (ry0 + prow) * WW + gcol;
            if      (val == 0) g_sum_x[p] = r;
            else if (val == 1) g_max_x[p] = r;
            else if (val == 2) g_sum_g[p] = r;
            else               g_max_g[p] = r;
        }
    }
}

// ---------------------------------------------------------------------------
// Kernel 2: fused gates. Blocks 0..799: spatial 7x7 conv (16x16 tiles).
// Blocks 800..807: channel MLP for batch (blk-800). block = 256.
// ---------------------------------------------------------------------------
#define STILE 16
#define SHALO 22
#define SHE (SHALO*SHALO)    // 484
__global__ __launch_bounds__(256) void k_gates(const float* __restrict__ w1,
                                               const float* __restrict__ w2,
                                               const float* __restrict__ sw,
                                               const float* __restrict__ sb,
                                               const float* __restrict__ alpha,
                                               const float* __restrict__ beta) {
    __shared__ float sm[4*SHE + 200];
    const int tid = threadIdx.x;
    const int blk = blockIdx.x;

    if (blk < 800) {
        const int bx = blk % 10, by = (blk / 10) % 10, b = blk / 100;
        const int tx0 = bx * STILE, ty0 = by * STILE;
        float* t   = sm;
        float* wsm = sm + 4*SHE;
        if (tid < 196) wsm[tid] = sw[tid];

        const int pbase = b * HW;
        const float invC = 1.f / CC;
        for (int i = tid; i < 4*SHE; i += 256) {
            int ch  = i / SHE;
            int rem = i - ch * SHE;
            int r   = rem / SHALO, cc2 = rem - r * SHALO;
            int gy  = ty0 - 3 + r, gx = tx0 - 3 + cc2;
            float v = 0.f;
            if ((unsigned)gy < HH && (unsigned)gx < WW) {
                int p = pbase + gy * WW + gx;
                if      (ch == 0) v = g_sum_x[p] * invC;
                else if (ch == 1) v = g_max_x[p];
                else if (ch == 2) v = g_sum_g[p] * invC;
                else              v = g_max_g[p];
            }
            t[i] = v;
        }
        __syncthreads();

        const int pr = tid >> 4, pc = tid & 15;
        float acc = sb[0];
        #pragma unroll
        for (int ch = 0; ch < 4; ch++) {
            #pragma unroll
            for (int u = 0; u < 7; u++) {
                const float* rp = &t[ch*SHE + (pr + u)*SHALO + pc];
                const float* wr = &wsm[ch*49 + u*7];
                #pragma unroll
                for (int v = 0; v < 7; v++) acc = fmaf(rp[v], wr[v], acc);
            }
        }
        g_s_map[pbase + (ty0 + pr)*WW + tx0 + pc] = 1.f / (1.f + __expf(-acc));
    } else {
        const int b = blk - 800;
        float* cv = sm;
        float* h  = sm + CC;
        cv[tid] = g_c_sum[b*CC + tid] * (1.f / HW);
        __syncthreads();
        if (tid < 16) {
            float acc = 0.f;
            for (int c2 = 0; c2 < CC; c2++) acc = fmaf(cv[c2], w1[tid*CC + c2], acc);
            h[tid] = fmaxf(acc, 0.f);
        }
        __syncthreads();
        float acc = 0.f;
        #pragma unroll
        for (int j = 0; j < 16; j++) acc = fmaf(h[j], w2[tid*16 + j], acc);
        g_w_gate[b*CC + tid] = 1.f / (1.f + __expf(-acc));
        if (b == 0 && tid == 0) {
            float av = alpha[0], bv = beta[0];
            g_ab[0] = (av > 20.f) ? av : log1pf(expf(av));
            g_ab[1] = (bv > 20.f) ? bv : log1pf(expf(bv));
        }
    }
}

// ---------------------------------------------------------------------------
// Kernel 3: streaming apply. out = x * (1 + a*s) * (1 + b*w). float4.
// ---------------------------------------------------------------------------
__global__ __launch_bounds__(256) void k_apply(const float* __restrict__ x,
                                               float* __restrict__ out) {
    const float a  = g_ab[0];
    const float bb = g_ab[1];
    const int hw4  = HW / 4;             // 6400
    const int chw4 = CC * hw4;           // 1638400
    int i4 = blockIdx.x * 256 + threadIdx.x;
    int b  = i4 / chw4;
    int r  = i4 - b * chw4;
    int c  = r / hw4;
    int p4 = r - c * hw4;
    float wg = fmaf(bb, g_w_gate[b*CC + c], 1.f);
    float4 s4 = ((const float4*)g_s_map)[b*hw4 + p4];
    float4 x4 = ((const float4*)x)[i4];
    float4 o;
    o.x = x4.x * fmaf(a, s4.x, 1.f) * wg;
    o.y = x4.y * fmaf(a, s4.y, 1.f) * wg;
    o.z = x4.z * fmaf(a, s4.z, 1.f) * wg;
    o.w = x4.w * fmaf(a, s4.w, 1.f) * wg;
    ((float4*)out)[i4] = o;
}

// ---------------------------------------------------------------------------
extern "C" void kernel_launch(void* const* d_in, const int* in_sizes, int n_in,
                              void* d_out, int out_size) {
    const float* x  = (const float*)d_in[0];
    const float* w1 = (const float*)d_in[1];
    const float* w2 = (const float*)d_in[2];
    const float* sw = (const float*)d_in[3];
    const float* sb = (const float*)d_in[4];
    const float* al = (const float*)d_in[5];
    const float* be = (const float*)d_in[6];
    float* out = (float*)d_out;

    zero_kernel<<<(BB*CC + 255)/256, 256>>>();
    dim3 g1(NXT, NYT, BB);
    k_edge<<<g1, 256>>>(x);
    k_gates<<<808, 256>>>(w1, w2, sw, sb, al, be);
    int total4 = BB * CC * HW / 4;
    k_apply<<<(total4 + 255)/256, 256>>>(x, out);
}

// round 8
// speedup vs baseline: 1.2009x; 1.1330x over previous
#include <cuda_runtime.h>
#include <cstdint>

#define BB 8
#define CC 256
#define HH 160
#define WW 160
#define HW (HH*WW)          // 25600

// edge kernel geometry: 32-col ALIGNED x 8-row tile; 8 warps split 256 channels
#define ETW 32
#define ETH 8
#define NXT 5               // 5*32 = 160, exact
#define NYT 20              // 20*8 = 160, exact
#define CPW 32              // channels per warp

// ---- scratch (no allocations allowed) ----
__device__ float g_c_sum[BB*CC];      // per-(b,c) sum of g
__device__ float g_w_gate[BB*CC];     // channel gate
__device__ float g_sum_x[BB*HW];      // per-pixel sum over channels of x
__device__ float g_sum_g[BB*HW];      // per-pixel sum over channels of g
__device__ float g_max_x[BB*HW];      // per-pixel max of x
__device__ float g_max_g[BB*HW];      // per-pixel max of g
__device__ float g_s_map[BB*HW];      // spatial gate
__device__ float g_ab[2];             // softplus(alpha), softplus(beta)

__device__ __forceinline__ float sqrt_approx(float v) {
    float r;
    asm("sqrt.approx.f32 %0, %1;" : "=f"(r) : "f"(v));
    return r;
}

__global__ void zero_kernel() {
    int i = blockIdx.x * 256 + threadIdx.x;
    if (i < BB*CC) g_c_sum[i] = 0.f;
}

// ---------------------------------------------------------------------------
// Kernel 1: Sobel magnitude + all reductions.
// Aligned 32-col tiles: lane == column, every main LDG is one fully-used
// 128B line. Edge lanes (0,31) fetch their out-of-segment neighbor with a
// 2-lane predicated LDG. Horizontal stage via shfl, vertical stage via a
// 3-row register window. 8 warps x 32 channels on the same 32x8 strip;
// cross-warp combine once per block via padded smem; plain global stores.
// grid (5, 20, 8), block 256.
// ---------------------------------------------------------------------------
__global__ __launch_bounds__(256) void k_edge(const float* __restrict__ x) {
    __shared__ float cmb[8*1028];           // [warp][stat*256+px], pad 1028

    const int tid  = threadIdx.x;
    const int lane = tid & 31;
    const int wid  = tid >> 5;
    const int tx0  = blockIdx.x * ETW;
    const int ry0  = blockIdx.y * ETH;
    const int b    = blockIdx.z;

    const int col = tx0 + lane;             // always < WW
    const bool eact = ((lane == 0) && (col > 0)) ||
                      ((lane == 31) && (col + 1 < WW));
    const int  eoff = (lane == 0) ? -1 : 1;

    float sx[ETH], sg[ETH], mx[ETH], mg[ETH];
    #pragma unroll
    for (int k = 0; k < ETH; k++) {
        sx[k] = 0.f; sg[k] = 0.f; mx[k] = -3.4e38f; mg[k] = 0.f;
    }

    const bool rm1ok = (ry0 > 0);
    const bool rp8ok = (ry0 + ETH < HH);

    const float* xb = x + ((size_t)b * CC + (size_t)wid * CPW) * HW + col;

    for (int ch = 0; ch < CPW; ch++) {
        const float* xc = xb + (size_t)ch * HW;
        float cs = 0.f;

        // prologue rows ry0-1, ry0
        float v, e, xl, xr;
        {
            const float* p = xc + (size_t)(ry0 - 1) * WW;
            v = rm1ok ? p[0] : 0.f;
            e = (rm1ok && eact) ? p[eoff] : 0.f;
        }
        xl = __shfl_up_sync(0xffffffffu, v, 1);   if (lane == 0)  xl = e;
        xr = __shfl_down_sync(0xffffffffu, v, 1); if (lane == 31) xr = e;
        float hdA = xl - xr;
        float hsA = fmaf(2.f, v, xl) + xr;

        {
            const float* p = xc + (size_t)ry0 * WW;
            v = p[0];
            e = eact ? p[eoff] : 0.f;
        }
        xl = __shfl_up_sync(0xffffffffu, v, 1);   if (lane == 0)  xl = e;
        xr = __shfl_down_sync(0xffffffffu, v, 1); if (lane == 31) xr = e;
        float hdB = xl - xr;
        float hsB = fmaf(2.f, v, xl) + xr;
        float xprev = v;

        #pragma unroll
        for (int k = 0; k < ETH; k++) {
            bool rok = (k < ETH-1) || rp8ok;      // row ry0+k+1
            {
                const float* p = xc + (size_t)(ry0 + k + 1) * WW;
                v = rok ? p[0] : 0.f;
                e = (rok && eact) ? p[eoff] : 0.f;
            }
            xl = __shfl_up_sync(0xffffffffu, v, 1);   if (lane == 0)  xl = e;
            xr = __shfl_down_sync(0xffffffffu, v, 1); if (lane == 31) xr = e;
            float hdC = xl - xr;
            float hsC = fmaf(2.f, v, xl) + xr;

            float gx = fmaf(2.f, hdB, hdA) + hdC;  // 4*true gx
            float gy = hsA - hsC;                  // 4*true gy
            float g  = 0.25f * sqrt_approx(fmaf(gy, gy, fmaf(gx, gx, 1.6e-11f)));

            sx[k] += xprev;  mx[k] = fmaxf(mx[k], xprev);
            sg[k] += g;      mg[k] = fmaxf(mg[k], g);
            cs += g;

            hdA = hdB; hdB = hdC; hsA = hsB; hsB = hsC; xprev = v;
        }

        // per-channel spatial sum (all lanes valid)
        #pragma unroll
        for (int off = 16; off; off >>= 1)
            cs += __shfl_xor_sync(0xffffffffu, cs, off);
        if (lane == 0)
            atomicAdd(&g_c_sum[b*CC + wid*CPW + ch], cs);
    }

    // cross-warp combine of per-pixel stats (once per block)
    {
        float* mybuf = cmb + wid * 1028;
        #pragma unroll
        for (int k = 0; k < ETH; k++) {
            int px = k * 32 + lane;
            mybuf[0*256 + px] = sx[k];
            mybuf[1*256 + px] = mx[k];
            mybuf[2*256 + px] = sg[k];
            mybuf[3*256 + px] = mg[k];
        }
    }
    __syncthreads();

    #pragma unroll
    for (int val = 0; val < 4; val++) {
        int px = tid;                       // 256 threads, 256 px
        bool ismax = (val & 1);
        float r = cmb[0*1028 + val*256 + px];
        #pragma unroll
        for (int w = 1; w < 8; w++) {
            float t = cmb[w*1028 + val*256 + px];
            r = ismax ? fmaxf(r, t) : (r + t);
        }
        int prow = px >> 5, pcol = px & 31;
        int p = b * HW + (ry0 + prow) * WW + tx0 + pcol;
        if      (val == 0) g_sum_x[p] = r;
        else if (val == 1) g_max_x[p] = r;
        else if (val == 2) g_sum_g[p] = r;
        else               g_max_g[p] = r;
    }
}

// ---------------------------------------------------------------------------
// Kernel 2: fused gates. Blocks 0..799: spatial 7x7 conv (16x16 tiles).
// Blocks 800..807: channel MLP for batch (blk-800). block = 256.
// ---------------------------------------------------------------------------
#define STILE 16
#define SHALO 22
#define SHE (SHALO*SHALO)    // 484
__global__ __launch_bounds__(256) void k_gates(const float* __restrict__ w1,
                                               const float* __restrict__ w2,
                                               const float* __restrict__ sw,
                                               const float* __restrict__ sb,
                                               const float* __restrict__ alpha,
                                               const float* __restrict__ beta) {
    __shared__ float sm[4*SHE + 200];
    const int tid = threadIdx.x;
    const int blk = blockIdx.x;

    if (blk < 800) {
        const int bx = blk % 10, by = (blk / 10) % 10, b = blk / 100;
        const int tx0 = bx * STILE, ty0 = by * STILE;
        float* t   = sm;
        float* wsm = sm + 4*SHE;
        if (tid < 196) wsm[tid] = sw[tid];

        const int pbase = b * HW;
        const float invC = 1.f / CC;
        for (int i = tid; i < 4*SHE; i += 256) {
            int ch  = i / SHE;
            int rem = i - ch * SHE;
            int r   = rem / SHALO, cc2 = rem - r * SHALO;
            int gy  = ty0 - 3 + r, gx = tx0 - 3 + cc2;
            float v = 0.f;
            if ((unsigned)gy < HH && (unsigned)gx < WW) {
                int p = pbase + gy * WW + gx;
                if      (ch == 0) v = g_sum_x[p] * invC;
                else if (ch == 1) v = g_max_x[p];
                else if (ch == 2) v = g_sum_g[p] * invC;
                else              v = g_max_g[p];
            }
            t[i] = v;
        }
        __syncthreads();

        const int pr = tid >> 4, pc = tid & 15;
        float acc = sb[0];
        #pragma unroll
        for (int ch = 0; ch < 4; ch++) {
            #pragma unroll
            for (int u = 0; u < 7; u++) {
                const float* rp = &t[ch*SHE + (pr + u)*SHALO + pc];
                const float* wr = &wsm[ch*49 + u*7];
                #pragma unroll
                for (int v = 0; v < 7; v++) acc = fmaf(rp[v], wr[v], acc);
            }
        }
        g_s_map[pbase + (ty0 + pr)*WW + tx0 + pc] = 1.f / (1.f + __expf(-acc));
    } else {
        const int b = blk - 800;
        float* cv = sm;
        float* h  = sm + CC;
        cv[tid] = g_c_sum[b*CC + tid] * (1.f / HW);
        __syncthreads();
        if (tid < 16) {
            float acc = 0.f;
            for (int c2 = 0; c2 < CC; c2++) acc = fmaf(cv[c2], w1[tid*CC + c2], acc);
            h[tid] = fmaxf(acc, 0.f);
        }
        __syncthreads();
        float acc = 0.f;
        #pragma unroll
        for (int j = 0; j < 16; j++) acc = fmaf(h[j], w2[tid*16 + j], acc);
        g_w_gate[b*CC + tid] = 1.f / (1.f + __expf(-acc));
        if (b == 0 && tid == 0) {
            float av = alpha[0], bv = beta[0];
            g_ab[0] = (av > 20.f) ? av : log1pf(expf(av));
            g_ab[1] = (bv > 20.f) ? bv : log1pf(expf(bv));
        }
    }
}

// ---------------------------------------------------------------------------
// Kernel 3: streaming apply. out = x * (1 + a*s) * (1 + b*w). float4,
// streaming cache hints (no reuse of x or out).
// ---------------------------------------------------------------------------
__global__ __launch_bounds__(256) void k_apply(const float* __restrict__ x,
                                               float* __restrict__ out) {
    const float a  = g_ab[0];
    const float bb = g_ab[1];
    const int hw4  = HW / 4;             // 6400
    int i4 = blockIdx.x * 256 + threadIdx.x;
    int cl = i4 / hw4;                   // b*CC + c   (0..2047)
    int b  = cl >> 8;
    int p4 = i4 - cl * hw4;
    float wg = fmaf(bb, g_w_gate[cl], 1.f);
    float4 s4 = ((const float4*)g_s_map)[b*hw4 + p4];
    float4 x4 = __ldcs((const float4*)x + i4);
    float4 o;
    o.x = x4.x * fmaf(a, s4.x, 1.f) * wg;
    o.y = x4.y * fmaf(a, s4.y, 1.f) * wg;
    o.z = x4.z * fmaf(a, s4.z, 1.f) * wg;
    o.w = x4.w * fmaf(a, s4.w, 1.f) * wg;
    __stcs((float4*)out + i4, o);
}

// ---------------------------------------------------------------------------
extern "C" void kernel_launch(void* const* d_in, const int* in_sizes, int n_in,
                              void* d_out, int out_size) {
    const float* x  = (const float*)d_in[0];
    const float* w1 = (const float*)d_in[1];
    const float* w2 = (const float*)d_in[2];
    const float* sw = (const float*)d_in[3];
    const float* sb = (const float*)d_in[4];
    const float* al = (const float*)d_in[5];
    const float* be = (const float*)d_in[6];
    float* out = (float*)d_out;

    zero_kernel<<<(BB*CC + 255)/256, 256>>>();
    dim3 g1(NXT, NYT, BB);
    k_edge<<<g1, 256>>>(x);
    k_gates<<<808, 256>>>(w1, w2, sw, sb, al, be);
    int total4 = BB * CC * HW / 4;
    k_apply<<<(total4 + 255)/256, 256>>>(x, out);
}